// round 17
// baseline (speedup 1.0000x reference)
#include <cuda_runtime.h>
#include <math.h>
#include <stdint.h>

// Problem constants (match reference)
#define N_INPUTSC 2048
#define UNITSC    2048
#define LC        8
#define FANINC    4096
#define TOTALC    18432

#define KC      128           // partial-sum depth (k-chunks of 32 rows)
#define RPC     32            // rows per chunk
#define JT      8             // column tiles of 256
#define CPB     256           // cols per tile (1KB per row slice)
#define GEMV_BLOCKS (KC * JT) // 1024
#define MAT_BLOCKS  8

// Persistent scratch (allocation-free rule: __device__ globals)
__device__ float g_partial[2][KC * UNITSC];  // ping-pong partials, 1MB each
__device__ float g_outputs[TOTALC];          // materialized state vector

// Sum the KC partials for column u of the previous layer (L2-resident).
__device__ __forceinline__ float sum_partials(const float* __restrict__ P, int u) {
    float s0 = 0.f, s1 = 0.f, s2 = 0.f, s3 = 0.f;
#pragma unroll 8
    for (int c = 0; c < KC; c += 4) {
        s0 += P[(size_t)(c    ) * UNITSC + u];
        s1 += P[(size_t)(c + 1) * UNITSC + u];
        s2 += P[(size_t)(c + 2) * UNITSC + u];
        s3 += P[(size_t)(c + 3) * UNITSC + u];
    }
    return (s0 + s1) + (s2 + s3);
}

// ---- mbarrier / bulk-copy helpers ----
__device__ __forceinline__ uint32_t smem_u32(const void* p) {
    return (uint32_t)__cvta_generic_to_shared(p);
}
__device__ __forceinline__ void mbar_init(uint32_t mbar, uint32_t count) {
    asm volatile("mbarrier.init.shared.b64 [%0], %1;" :: "r"(mbar), "r"(count) : "memory");
}
__device__ __forceinline__ void mbar_expect_tx(uint32_t mbar, uint32_t bytes) {
    asm volatile("mbarrier.arrive.expect_tx.shared.b64 _, [%0], %1;"
                 :: "r"(mbar), "r"(bytes) : "memory");
}
__device__ __forceinline__ void bulk_copy(uint32_t dst, const void* src,
                                          uint32_t bytes, uint32_t mbar) {
    asm volatile("cp.async.bulk.shared::cta.global.mbarrier::complete_tx::bytes "
                 "[%0], [%1], %2, [%3];"
                 :: "r"(dst), "l"(src), "r"(bytes), "r"(mbar) : "memory");
}
__device__ __forceinline__ void mbar_wait(uint32_t mbar, uint32_t parity) {
    asm volatile(
        "{\n\t"
        ".reg .pred P;\n\t"
        "WL%=:\n\t"
        "mbarrier.try_wait.parity.acquire.cta.shared::cta.b64 P, [%0], %1, 0x989680;\n\t"
        "@P bra WD%=;\n\t"
        "bra WL%=;\n\t"
        "WD%=:\n\t"
        "}"
        :: "r"(mbar), "r"(parity) : "memory");
}

// ---------------------------------------------------------------------------
// fused layer kernel, one launch per layer.
//  - blocks [0, 1024): gemv. Block (kc, jt): rows [kc*32,+32), cols
//    [jt*256,+256). Warp 0: load node_inds, ballot liveness, lane0
//    expect_tx(live*1024), live lanes issue ONE cp.async.bulk (1KB) each —
//    dead rows generate no instruction and no traffic; then gather values.
//    All threads mbarrier-wait, consume live rows from smem, R11 epilogue.
//  - blocks [1024, 1032): materialize slice `layer` into g_outputs.
// ---------------------------------------------------------------------------
__global__ __launch_bounds__(256) void layer_kernel(
    int layer,
    const float* __restrict__ x,
    const int*   __restrict__ node_inds,
    const float* __restrict__ Ws,
    const float* __restrict__ bs)
{
    const int tid  = threadIdx.x;
    const int base = layer << 11;
    const float* Pprev = g_partial[(layer + 1) & 1];
    const float* bprev = bs + (layer - 1) * UNITSC;

    if (blockIdx.x >= GEMV_BLOCKS) {
        // ---- materialize slice `layer` ----
        int u = (blockIdx.x - GEMV_BLOCKS) * 256 + tid;
        float o;
        if (layer == 0) o = x[u];
        else            o = tanhf(sum_partials(Pprev, u) + bprev[u]);
        g_outputs[base + u] = o;
        return;
    }

    const int kc = blockIdx.x >> 3;
    const int jt = blockIdx.x & 7;

    __shared__ float             sg[RPC];
    __shared__ __align__(16) float tile[RPC * CPB];   // 32KB staged W tile
    __shared__ float4            red[3][64];
    __shared__ __align__(8) unsigned long long mbar;

    const uint32_t mb = smem_u32(&mbar);
    if (tid == 0) mbar_init(mb, 1);
    __syncthreads();                                  // mbar visible to all

    // ---- warp 0: liveness ballot -> bulk copies -> value gather ----
    if (tid < 32) {
        int idx = node_inds[layer * FANINC + kc * RPC + tid];
        bool live = (idx < base + UNITSC);
        unsigned m = __ballot_sync(0xffffffffu, live);
        if (tid == 0) mbar_expect_tx(mb, (uint32_t)__popc(m) * (CPB * 4));
        __syncwarp();
        if (live) {
            const float* src = Ws + ((size_t)layer * FANINC + kc * RPC + tid) * UNITSC
                             + jt * CPB;
            bulk_copy(smem_u32(tile + tid * CPB), src, CPB * 4, mb);
        }
        // gather value (current slice recomputes from prev partials)
        float v = 0.f;
        if (idx < base) {
            v = g_outputs[idx];
        } else if (live) {
            int u = idx - base;
            if (layer == 0) v = x[u];
            else            v = tanhf(sum_partials(Pprev, u) + bprev[u]);
        }
        sg[tid] = v;
    }
    __syncthreads();                                  // sg ready
    mbar_wait(mb, 0);                                 // tile ready

    // ---- consume: 4 groups x 8 rows x 64 float4-cols ----
    const int tx = tid & 63;
    const int tg = tid >> 6;

    float ax = 0.f, ay = 0.f, az = 0.f, aw = 0.f;
#pragma unroll
    for (int i = 0; i < 8; ++i) {
        int   r  = tg * 8 + i;
        float gk = sg[r];
        if (gk != 0.f) {                              // dead rows never read
            float4 w = *reinterpret_cast<const float4*>(tile + r * CPB + tx * 4);
            ax = fmaf(gk, w.x, ax);
            ay = fmaf(gk, w.y, ay);
            az = fmaf(gk, w.z, az);
            aw = fmaf(gk, w.w, aw);
        }
    }

    if (tg > 0) red[tg - 1][tx] = make_float4(ax, ay, az, aw);
    __syncthreads();
    if (tg == 0) {
#pragma unroll
        for (int r = 0; r < 3; ++r) {
            float4 p = red[r][tx];
            ax += p.x; ay += p.y; az += p.z; aw += p.w;
        }
        *reinterpret_cast<float4*>(g_partial[layer & 1]
                                   + kc * UNITSC + jt * CPB + tx * 4) =
            make_float4(ax, ay, az, aw);
    }
}

// ---------------------------------------------------------------------------
// final: out = tanh(colsum(layer-7 partials) + b7)
// ---------------------------------------------------------------------------
__global__ __launch_bounds__(256) void final_kernel(
    const float* __restrict__ bs, float* __restrict__ out)
{
    int u = blockIdx.x * 256 + threadIdx.x;
    const float* P = g_partial[(LC - 1) & 1];
    out[u] = tanhf(sum_partials(P, u) + bs[(LC - 1) * UNITSC + u]);
}

extern "C" void kernel_launch(void* const* d_in, const int* in_sizes, int n_in,
                              void* d_out, int out_size) {
    const float* x  = (const float*)d_in[0];   // [2048] f32
    const int*   ni = (const int*)d_in[1];     // [8, 4096] i32
    const float* Ws = (const float*)d_in[2];   // [8, 4096, 2048] f32
    const float* bs = (const float*)d_in[3];   // [8, 2048] f32
    float* out = (float*)d_out;                // [2048] f32

    for (int i = 0; i < LC; ++i) {
        layer_kernel<<<GEMV_BLOCKS + MAT_BLOCKS, 256>>>(i, x, ni, Ws, bs);
    }
    final_kernel<<<UNITSC / 256, 256>>>(bs, out);
}